// round 7
// baseline (speedup 1.0000x reference)
#include <cuda_runtime.h>

// TT-linear, R7: all P2 smem loads are either fully-coalesced-unique or
// fully-warp-uniform (the only two cheap classes per R4-R6 calibration).
// y[b,n1n2n3] = sum x[b,m1,m2,m3] c0[m1,n1,r1] c1[r1,m2,n2,r2] c2[r2,m3,n3] + bias
// B=4096, modes 16, ranks 8. 152 CTAs x 256 thr (2 row-groups of 128).
//
// T1 column semantic changed to col = r1*16 + n1 (consecutive n1!) so the
// A-operand for a warp's n1 set {4w..4w+3} is ONE uniform ulonglong2.
// Thread owns 4 n1 x 4 d (d = 4j..4j+3); B is one coalesced LDS.128 per k.

typedef unsigned long long u64;

__device__ __forceinline__ u64 pk2(float lo, float hi) {
    u64 d;
    asm("mov.b64 %0, {%1, %2};"
        : "=l"(d) : "r"(__float_as_uint(lo)), "r"(__float_as_uint(hi)));
    return d;
}
__device__ __forceinline__ float2 upk2(u64 v) {
    unsigned lo, hi;
    asm("mov.b64 {%0, %1}, %2;" : "=r"(lo), "=r"(hi) : "l"(v));
    return make_float2(__uint_as_float(lo), __uint_as_float(hi));
}
__device__ __forceinline__ u64 ffma2(u64 a, u64 b, u64 c) {
    u64 d;
    asm("fma.rn.f32x2 %0, %1, %2, %3;" : "=l"(d) : "l"(a), "l"(b), "l"(c));
    return d;
}
__device__ __forceinline__ void barg(int id) {
    asm volatile("bar.sync %0, 128;" :: "r"(id) : "memory");
}

__global__ __launch_bounds__(256, 1)
void tt_linear_kernel(const float* __restrict__ xg,
                      const float* __restrict__ c0g,
                      const float* __restrict__ c1g,
                      const float* __restrict__ c2g,
                      const float* __restrict__ biasg,
                      float* __restrict__ outg)
{
    extern __shared__ float smem[];
    // cores (shared by both groups)
    float* c0s = smem;            // 2048  : [m1*128 + n1*8 + r1]
    float* c1s = smem + 2048;     // 16384 : [(r1*16+m2)*128 + n2*8 + r2]
    float* c2s = smem + 18432;    // 2048  : [mpg*256 + (n3*8+r2)*2 + plane]
    const int tid = threadIdx.x;
    const int g = tid >> 7;       // row group 0/1
    const int t = tid & 127;      // thread within group
    // per-group: xs 2*520, T1 2*4096, T2 2*4096 = 17424 floats
    float* xs  = smem + 20480 + g * 17424;  // [pp*520 + (m1*16+m2)*2 + plane]
    float* T1s = xs + 1040;                 // [pp*4096 + (m2*128 + col)*2 + plane], col = r1*16+n1
    float* T2t = T1s + 8192;                // [pp*4096 + (r2*256 + n1*16 + n2)*2 + plane]

    // ---- stage cores (once per CTA) ----
    for (int i = tid; i < 2048; i += 256) c0s[i] = c0g[i];
    for (int i = tid; i < 16384; i += 256) c1s[i] = c1g[i];
    for (int i = tid; i < 2048; i += 256) {
        int mpg = i >> 8;
        int rem = i & 255;
        int plane = rem & 1;
        int idx = rem >> 1;            // n3*8 + r2
        int n3 = idx >> 3, r2 = idx & 7;
        c2s[i] = c2g[r2 * 256 + (2 * mpg + plane) * 16 + n3];
    }
    __syncthreads();

    // c0 column for this thread. Thread t produces T1 col t = r1*16 + n1:
    //   n1 = t & 15, r1 = t >> 4 -> c0 element [m1][n1*8 + r1]
    float c0col[16];
    {
        const int n1t = t & 15, r1t = t >> 4;
#pragma unroll
        for (int m1 = 0; m1 < 16; ++m1)
            c0col[m1] = c0s[m1 * 128 + n1t * 8 + r1t];
    }

    const int w = t >> 5;   // warp in group -> n1 set {4w..4w+3}
    const int j = t & 31;   // lane -> d set {4j..4j+3}
    const int mybar = g + 1;

    const int strideR = gridDim.x * 2;
    const int iters = (4096 + strideR - 1) / strideR;   // uniform (barrier-safe)

    for (int it = 0; it < iters; ++it) {
        const int row = blockIdx.x * 2 + g + it * strideR;
        const bool active = row < 4096;
        const int rc = active ? row : 4095;

        float acc[32];
#pragma unroll
        for (int q = 0; q < 32; ++q) acc[q] = 0.0f;

        const float4* xrow4 = (const float4*)(xg + (size_t)rc * 4096);

#pragma unroll 1
        for (int qp = 0; qp < 4; ++qp) {    // pass: planes 4qp..4qp+3 (pp = 0,1)
            // ---- load x for this pass, pair-interleave into xs ----
            {
                float4 v0 = xrow4[t * 4 + qp];           // m1m2 = t
                float4 v1 = xrow4[(t + 128) * 4 + qp];   // m1m2 = t+128
                *(float2*)(xs + t * 2)               = make_float2(v0.x, v0.y);
                *(float2*)(xs + 520 + t * 2)         = make_float2(v0.z, v0.w);
                *(float2*)(xs + (t + 128) * 2)       = make_float2(v1.x, v1.y);
                *(float2*)(xs + 520 + (t + 128) * 2) = make_float2(v1.z, v1.w);
            }
            barg(mybar);

            // ===== Phase 1: T1 pairs for pp = 0,1 (col = t) =====
#pragma unroll
            for (int pp = 0; pp < 2; ++pp) {
                u64 t1p[16];
#pragma unroll
                for (int m2 = 0; m2 < 16; ++m2) t1p[m2] = 0ULL;
                const float* xp = xs + pp * 520;
#pragma unroll 4
                for (int m1 = 0; m1 < 16; ++m1) {
                    const u64 cvp = pk2(c0col[m1], c0col[m1]);
                    const ulonglong2* qv = (const ulonglong2*)(xp + m1 * 32);
#pragma unroll
                    for (int qq = 0; qq < 8; ++qq) {
                        ulonglong2 v = qv[qq];          // uniform broadcast LDS.128
                        t1p[2 * qq]     = ffma2(v.x, cvp, t1p[2 * qq]);
                        t1p[2 * qq + 1] = ffma2(v.y, cvp, t1p[2 * qq + 1]);
                    }
                }
                float* T1p = T1s + pp * 4096;
#pragma unroll
                for (int m2 = 0; m2 < 16; ++m2)
                    *(u64*)(T1p + (m2 * 128 + t) * 2) = t1p[m2];
            }
            barg(mybar);

            // ===== Phase 2: both pair-planes =====
            // q2[pp][a*4 + c]: n1 = 4w+a, d = 4j+c, value = (plane0, plane1)
            u64 q2[2][16];
#pragma unroll
            for (int q = 0; q < 16; ++q) { q2[0][q] = 0ULL; q2[1][q] = 0ULL; }

            {
                const float* bbase = c1s + 4 * j;                  // + k*128
                const float* abase = T1s + (4 * w) * 2;            // + (m2*128 + r1*16)*2 (+4096 pp)
#pragma unroll 1
                for (int m2 = 0; m2 < 16; ++m2) {
                    const float* bm = bbase + m2 * 128;            // + r1*2048
                    const float* am = abase + m2 * 256;            // + r1*32
#pragma unroll 4
                    for (int r1 = 0; r1 < 8; ++r1) {
                        // B: fully coalesced LDS.128 (512B unique per warp)
                        float4 bf = *(const float4*)(bm + r1 * 2048);
                        u64 b0 = pk2(bf.x, bf.x);
                        u64 b1 = pk2(bf.y, bf.y);
                        u64 b2 = pk2(bf.z, bf.z);
                        u64 b3 = pk2(bf.w, bf.w);
#pragma unroll
                        for (int pp = 0; pp < 2; ++pp) {
                            const float* ap = am + pp * 4096 + r1 * 32;
                            // A: warp-uniform ulonglong2 (n1 = 4w..4w+3 pairs)
                            ulonglong2 a01 = *(const ulonglong2*)(ap);
                            ulonglong2 a23 = *(const ulonglong2*)(ap + 4);
                            q2[pp][0]  = ffma2(a01.x, b0, q2[pp][0]);
                            q2[pp][1]  = ffma2(a01.x, b1, q2[pp][1]);
                            q2[pp][2]  = ffma2(a01.x, b2, q2[pp][2]);
                            q2[pp][3]  = ffma2(a01.x, b3, q2[pp][3]);
                            q2[pp][4]  = ffma2(a01.y, b0, q2[pp][4]);
                            q2[pp][5]  = ffma2(a01.y, b1, q2[pp][5]);
                            q2[pp][6]  = ffma2(a01.y, b2, q2[pp][6]);
                            q2[pp][7]  = ffma2(a01.y, b3, q2[pp][7]);
                            q2[pp][8]  = ffma2(a23.x, b0, q2[pp][8]);
                            q2[pp][9]  = ffma2(a23.x, b1, q2[pp][9]);
                            q2[pp][10] = ffma2(a23.x, b2, q2[pp][10]);
                            q2[pp][11] = ffma2(a23.x, b3, q2[pp][11]);
                            q2[pp][12] = ffma2(a23.y, b0, q2[pp][12]);
                            q2[pp][13] = ffma2(a23.y, b1, q2[pp][13]);
                            q2[pp][14] = ffma2(a23.y, b2, q2[pp][14]);
                            q2[pp][15] = ffma2(a23.y, b3, q2[pp][15]);
                        }
                    }
                }
            }
            // transposed store: T2t[pp*4096 + ((d&7)*256 + n1*16 + (d>>3))*2]
#pragma unroll
            for (int pp = 0; pp < 2; ++pp) {
                float* T2p = T2t + pp * 4096;
#pragma unroll
                for (int a = 0; a < 4; ++a) {
                    const int n1 = 4 * w + a;
#pragma unroll
                    for (int c = 0; c < 4; ++c) {
                        const int d = 4 * j + c;
                        const int addr = ((d & 7) * 256 + n1 * 16 + (d >> 3)) * 2;
                        *(u64*)(T2p + addr) = q2[pp][a * 4 + c];
                    }
                }
            }
            barg(mybar);

            // ===== Phase 3: accumulate output (both pp) =====
#pragma unroll
            for (int pp = 0; pp < 2; ++pp) {
                const float* T2p = T2t + pp * 4096;
                u64 tv0[8], tv1[8];
#pragma unroll
                for (int r2 = 0; r2 < 8; ++r2) {
                    tv0[r2] = *(const u64*)(T2p + (r2 * 256 + t) * 2);       // coalesced
                    tv1[r2] = *(const u64*)(T2p + (r2 * 256 + t + 128) * 2);
                }
                const float* c2p = c2s + (2 * qp + pp) * 256;
#pragma unroll
                for (int n3 = 0; n3 < 16; ++n3) {
                    u64 a0 = 0ULL, a1 = 0ULL;
#pragma unroll
                    for (int r2p = 0; r2p < 4; ++r2p) {
                        ulonglong2 cp = *(const ulonglong2*)
                            (c2p + (n3 * 8 + 2 * r2p) * 2);   // uniform broadcast
                        a0 = ffma2(tv0[2 * r2p],     cp.x, a0);
                        a0 = ffma2(tv0[2 * r2p + 1], cp.y, a0);
                        a1 = ffma2(tv1[2 * r2p],     cp.x, a1);
                        a1 = ffma2(tv1[2 * r2p + 1], cp.y, a1);
                    }
                    float2 f0 = upk2(a0), f1 = upk2(a1);
                    acc[n3]      += f0.x + f0.y;
                    acc[16 + n3] += f1.x + f1.y;
                }
            }
            // next pass's post-P1 barrier orders these T2t reads vs new writes.
        }

        // ---- add bias, store row ----
        if (active) {
            float* og = outg + (size_t)row * 4096;
#pragma unroll
            for (int q = 0; q < 4; ++q) {
                float4 b4 = *(const float4*)(biasg + t * 16 + 4 * q);
                float4 v;
                v.x = acc[4 * q + 0] + b4.x;
                v.y = acc[4 * q + 1] + b4.y;
                v.z = acc[4 * q + 2] + b4.z;
                v.w = acc[4 * q + 3] + b4.w;
                *(float4*)(og + t * 16 + 4 * q) = v;
            }
#pragma unroll
            for (int q = 0; q < 4; ++q) {
                float4 b4 = *(const float4*)(biasg + (t + 128) * 16 + 4 * q);
                float4 v;
                v.x = acc[16 + 4 * q + 0] + b4.x;
                v.y = acc[16 + 4 * q + 1] + b4.y;
                v.z = acc[16 + 4 * q + 2] + b4.z;
                v.w = acc[16 + 4 * q + 3] + b4.w;
                *(float4*)(og + (t + 128) * 16 + 4 * q) = v;
            }
        }
    }
}

extern "C" void kernel_launch(void* const* d_in, const int* in_sizes, int n_in,
                              void* d_out, int out_size)
{
    const float* x    = (const float*)d_in[0];
    const float* c0   = (const float*)d_in[1];
    const float* c1   = (const float*)d_in[2];
    const float* c2   = (const float*)d_in[3];
    const float* bias = (const float*)d_in[4];
    float* out = (float*)d_out;

    // 20480 (cores) + 2 * 17424 (xs + T1 + T2 per group) = 55328 floats = 221312 B
    const int smem_bytes = 55328 * (int)sizeof(float);
    cudaFuncSetAttribute(tt_linear_kernel,
                         cudaFuncAttributeMaxDynamicSharedMemorySize, smem_bytes);

    tt_linear_kernel<<<152, 256, smem_bytes>>>(x, c0, c1, c2, bias, out);
}

// round 8
// speedup vs baseline: 1.0136x; 1.0136x over previous
#include <cuda_runtime.h>

// TT-linear, R8: occupancy doubled at constant smem by parallelizing the
// pair-plane (pp) dimension across warps instead of serializing it.
// 512 threads = 2 super-groups x 256; within a super-group, warps 0-3 own
// pp0 and warps 4-7 own pp1 of the same row & pass. Same T1/T2 buffers as R7.
// x LDG for pass p+1 is prefetched under pass p's P2 compute.
//
// y[b,n1n2n3] = sum x[b,m1,m2,m3] c0[m1,n1,r1] c1[r1,m2,n2,r2] c2[r2,m3,n3] + bias
// B=4096, modes 16, ranks 8. 152 CTAs x 512 thr.

typedef unsigned long long u64;

__device__ __forceinline__ u64 pk2(float lo, float hi) {
    u64 d;
    asm("mov.b64 %0, {%1, %2};"
        : "=l"(d) : "r"(__float_as_uint(lo)), "r"(__float_as_uint(hi)));
    return d;
}
__device__ __forceinline__ float2 upk2(u64 v) {
    unsigned lo, hi;
    asm("mov.b64 {%0, %1}, %2;" : "=r"(lo), "=r"(hi) : "l"(v));
    return make_float2(__uint_as_float(lo), __uint_as_float(hi));
}
__device__ __forceinline__ u64 ffma2(u64 a, u64 b, u64 c) {
    u64 d;
    asm("fma.rn.f32x2 %0, %1, %2, %3;" : "=l"(d) : "l"(a), "l"(b), "l"(c));
    return d;
}
__device__ __forceinline__ void barg(int id) {
    asm volatile("bar.sync %0, 256;" :: "r"(id) : "memory");
}

__global__ __launch_bounds__(512, 1)
void tt_linear_kernel(const float* __restrict__ xg,
                      const float* __restrict__ c0g,
                      const float* __restrict__ c1g,
                      const float* __restrict__ c2g,
                      const float* __restrict__ biasg,
                      float* __restrict__ outg)
{
    extern __shared__ float smem[];
    // cores (shared by both super-groups)
    float* c0s = smem;            // 2048  : [m1*128 + n1*8 + r1]
    float* c1s = smem + 2048;     // 16384 : [(r1*16+m2)*128 + n2*8 + r2]
    float* c2s = smem + 18432;    // 2048  : [mpg*256 + (n3*8+r2)*2 + plane]
    const int tid = threadIdx.x;
    const int g  = tid >> 8;      // super-group (row) 0/1
    const int u  = tid & 255;     // thread within super-group
    const int pc = u >> 7;        // pair-plane owned by this warp-half
    const int tc = u & 127;       // column thread within pp
    // per-sg: xs 2*520, T1 2*4096, T2 2*4096 = 17424 floats
    float* xs  = smem + 20480 + g * 17424;  // [pp*520 + (m1*16+m2)*2 + plane]
    float* T1s = xs + 1040;                 // [pp*4096 + (m2*128 + col)*2 + plane], col = r1*16+n1
    float* T2t = T1s + 8192;                // [pp*4096 + (r2*256 + n1*16 + n2)*2 + plane]

    // ---- stage cores (once per CTA) ----
    for (int i = tid; i < 2048; i += 512) c0s[i] = c0g[i];
    for (int i = tid; i < 16384; i += 512) c1s[i] = c1g[i];
    for (int i = tid; i < 2048; i += 512) {
        int mpg = i >> 8;
        int rem = i & 255;
        int plane = rem & 1;
        int idx = rem >> 1;            // n3*8 + r2
        int n3 = idx >> 3, r2 = idx & 7;
        c2s[i] = c2g[r2 * 256 + (2 * mpg + plane) * 16 + n3];
    }
    __syncthreads();

    // c0 column: T1 col = tc = r1*16 + n1  ->  c0[m1][n1*8 + r1]
    float c0col[16];
    {
        const int n1t = tc & 15, r1t = tc >> 4;
#pragma unroll
        for (int m1 = 0; m1 < 16; ++m1)
            c0col[m1] = c0s[m1 * 128 + n1t * 8 + r1t];
    }

    const int wq = (u >> 5) & 3;  // warp within pp -> n1 set {4wq..4wq+3}
    const int j  = u & 31;        // lane -> d set {4j..4j+3}
    const int mybar = g + 1;

    const int strideR = gridDim.x * 2;
    const int iters = (4096 + strideR - 1) / strideR;   // uniform (barrier-safe)
    const int bid2 = blockIdx.x * 2 + g;

    // flat-pass x address: pass p -> (iter p>>2, qp p&3)
    auto xfetch = [&](int p) -> float4 {
        int r = bid2 + (p >> 2) * strideR;
        if (r > 4095) r = 4095;
        const float4* xr4 = (const float4*)(xg + (size_t)r * 4096);
        return xr4[u * 4 + (p & 3)];
    };

    float4 xv = xfetch(0);   // prefetch pass 0

    for (int it = 0; it < iters; ++it) {
        const int row = bid2 + it * strideR;
        const bool active = row < 4096;

        float acc[16];
#pragma unroll
        for (int q = 0; q < 16; ++q) acc[q] = 0.0f;

#pragma unroll 1
        for (int qp = 0; qp < 4; ++qp) {    // pass: planes 4qp..4qp+3
            // ---- store prefetched x, pair-interleaved into xs ----
            *(float2*)(xs + u * 2)       = make_float2(xv.x, xv.y);   // pp0
            *(float2*)(xs + 520 + u * 2) = make_float2(xv.z, xv.w);   // pp1
            barg(mybar);

            // ===== Phase 1: T1 pairs for own pp (col = tc) =====
            {
                u64 t1p[16];
#pragma unroll
                for (int m2 = 0; m2 < 16; ++m2) t1p[m2] = 0ULL;
                const float* xp = xs + pc * 520;
#pragma unroll 4
                for (int m1 = 0; m1 < 16; ++m1) {
                    const u64 cvp = pk2(c0col[m1], c0col[m1]);
                    const ulonglong2* qv = (const ulonglong2*)(xp + m1 * 32);
#pragma unroll
                    for (int qq = 0; qq < 8; ++qq) {
                        ulonglong2 v = qv[qq];          // uniform broadcast LDS.128
                        t1p[2 * qq]     = ffma2(v.x, cvp, t1p[2 * qq]);
                        t1p[2 * qq + 1] = ffma2(v.y, cvp, t1p[2 * qq + 1]);
                    }
                }
                float* T1p = T1s + pc * 4096;
#pragma unroll
                for (int m2 = 0; m2 < 16; ++m2)
                    *(u64*)(T1p + (m2 * 128 + tc) * 2) = t1p[m2];
            }
            barg(mybar);

            // prefetch x for next pass (hidden under P2 compute)
            xv = xfetch(it * 4 + qp + 1);

            // ===== Phase 2: own pp; thread = 4 n1 x 4 d =====
            // q2[a*4+c]: n1 = 4wq+a, d = 4j+c, value = packed (planeA, planeB)
            u64 q2[16];
#pragma unroll
            for (int q = 0; q < 16; ++q) q2[q] = 0ULL;

            {
                const float* bbase = c1s + 4 * j;                 // + k*128
                const float* abase = T1s + pc * 4096 + (4 * wq) * 2;
#pragma unroll 1
                for (int m2 = 0; m2 < 16; ++m2) {
                    const float* bm = bbase + m2 * 128;           // + r1*2048
                    const float* am = abase + m2 * 256;           // + r1*32
#pragma unroll
                    for (int r1 = 0; r1 < 8; ++r1) {
                        float4 bf = *(const float4*)(bm + r1 * 2048);  // coalesced LDS.128
                        u64 b0 = pk2(bf.x, bf.x);
                        u64 b1 = pk2(bf.y, bf.y);
                        u64 b2 = pk2(bf.z, bf.z);
                        u64 b3 = pk2(bf.w, bf.w);
                        const float* ap = am + r1 * 32;
                        ulonglong2 a01 = *(const ulonglong2*)(ap);       // warp-uniform
                        ulonglong2 a23 = *(const ulonglong2*)(ap + 4);   // warp-uniform
                        q2[0]  = ffma2(a01.x, b0, q2[0]);
                        q2[1]  = ffma2(a01.x, b1, q2[1]);
                        q2[2]  = ffma2(a01.x, b2, q2[2]);
                        q2[3]  = ffma2(a01.x, b3, q2[3]);
                        q2[4]  = ffma2(a01.y, b0, q2[4]);
                        q2[5]  = ffma2(a01.y, b1, q2[5]);
                        q2[6]  = ffma2(a01.y, b2, q2[6]);
                        q2[7]  = ffma2(a01.y, b3, q2[7]);
                        q2[8]  = ffma2(a23.x, b0, q2[8]);
                        q2[9]  = ffma2(a23.x, b1, q2[9]);
                        q2[10] = ffma2(a23.x, b2, q2[10]);
                        q2[11] = ffma2(a23.x, b3, q2[11]);
                        q2[12] = ffma2(a23.y, b0, q2[12]);
                        q2[13] = ffma2(a23.y, b1, q2[13]);
                        q2[14] = ffma2(a23.y, b2, q2[14]);
                        q2[15] = ffma2(a23.y, b3, q2[15]);
                    }
                }
            }
            // transposed store into own pp's T2 plane
            {
                float* T2p = T2t + pc * 4096;
#pragma unroll
                for (int a = 0; a < 4; ++a) {
                    const int n1 = 4 * wq + a;
#pragma unroll
                    for (int c = 0; c < 4; ++c) {
                        const int d = 4 * j + c;
                        const int addr = ((d & 7) * 256 + n1 * 16 + (d >> 3)) * 2;
                        *(u64*)(T2p + addr) = q2[a * 4 + c];
                    }
                }
            }
            barg(mybar);

            // ===== Phase 3: accumulate output; thread owns pos = u =====
            {
                u64 tv0[8], tv1[8];
#pragma unroll
                for (int r2 = 0; r2 < 8; ++r2) {
                    tv0[r2] = *(const u64*)(T2t + (r2 * 256 + u) * 2);          // pp0, coalesced
                    tv1[r2] = *(const u64*)(T2t + 4096 + (r2 * 256 + u) * 2);   // pp1, coalesced
                }
                const float* c2p0 = c2s + (2 * qp) * 256;
                const float* c2p1 = c2p0 + 256;
#pragma unroll
                for (int n3 = 0; n3 < 16; ++n3) {
                    u64 a0 = 0ULL, a1 = 0ULL;
#pragma unroll
                    for (int r2p = 0; r2p < 4; ++r2p) {
                        ulonglong2 cp0 = *(const ulonglong2*)
                            (c2p0 + (n3 * 8 + 2 * r2p) * 2);   // uniform broadcast
                        ulonglong2 cp1 = *(const ulonglong2*)
                            (c2p1 + (n3 * 8 + 2 * r2p) * 2);
                        a0 = ffma2(tv0[2 * r2p],     cp0.x, a0);
                        a0 = ffma2(tv0[2 * r2p + 1], cp0.y, a0);
                        a1 = ffma2(tv1[2 * r2p],     cp1.x, a1);
                        a1 = ffma2(tv1[2 * r2p + 1], cp1.y, a1);
                    }
                    float2 f0 = upk2(a0), f1 = upk2(a1);
                    acc[n3] += (f0.x + f0.y) + (f1.x + f1.y);
                }
            }
            // T2 reads here vs next pass's P2 writes: ordered by next pass's
            // two barriers. xs overwrite at next pass top: P1 readers finished
            // two barriers ago.
        }

        // ---- add bias, store 16 outputs (pos = u) ----
        if (active) {
            float* og = outg + (size_t)row * 4096 + u * 16;
            const float* bp = biasg + u * 16;
#pragma unroll
            for (int q = 0; q < 4; ++q) {
                float4 b4 = *(const float4*)(bp + 4 * q);
                float4 v;
                v.x = acc[4 * q + 0] + b4.x;
                v.y = acc[4 * q + 1] + b4.y;
                v.z = acc[4 * q + 2] + b4.z;
                v.w = acc[4 * q + 3] + b4.w;
                *(float4*)(og + 4 * q) = v;
            }
        }
    }
}

extern "C" void kernel_launch(void* const* d_in, const int* in_sizes, int n_in,
                              void* d_out, int out_size)
{
    const float* x    = (const float*)d_in[0];
    const float* c0   = (const float*)d_in[1];
    const float* c1   = (const float*)d_in[2];
    const float* c2   = (const float*)d_in[3];
    const float* bias = (const float*)d_in[4];
    float* out = (float*)d_out;

    // 20480 (cores) + 2 * 17424 (xs + T1 + T2 per super-group) = 55328 floats
    const int smem_bytes = 55328 * (int)sizeof(float);   // 221312 B
    cudaFuncSetAttribute(tt_linear_kernel,
                         cudaFuncAttributeMaxDynamicSharedMemorySize, smem_bytes);

    tt_linear_kernel<<<152, 512, smem_bytes>>>(x, c0, c1, c2, bias, out);
}